// round 2
// baseline (speedup 1.0000x reference)
#include <cuda_runtime.h>
#include <math.h>

#define BATCH 128
#define N 256
#define NP1 (N + 1)
#define NUM_CLASSES 8
#define CE_COEFF 10.0f
#define UNCLAIMED 0x7FFFFFFF
#define BIGF 1e30f

__device__ float g_batch_loss[BATCH];

__device__ __forceinline__ float fsqrt_approx(float x) {
    float r;
    asm("sqrt.approx.f32 %0, %1;" : "=f"(r) : "f"(x));
    return r;
}

// One CTA per batch, 256 threads.
// Phase 1 (256 thr): column reduction init (v[j] = min_i cost(i,j), greedy claim).
// Phase 2 (warp 0):  exact shortest-augmenting-path (JV) for free rows only,
//                    absolute-distance Dijkstra, deferred dual updates,
//                    REDUX-based warp argmin, zero __syncthreads in inner loop.
// Phase 3 (256 thr): fused loss epilogue.
__global__ __launch_bounds__(N, 1) void hungarian_loss_kernel(
    const float* __restrict__ set1,   // [B, N, 3]
    const float* __restrict__ set2)   // [B, N, 10]
{
    const int b   = blockIdx.x;
    const int tid = threadIdx.x;
    const int lane = tid & 31;
    const int wid  = tid >> 5;

    __shared__ float s1x[N], s1y[N], s1l[N];
    __shared__ float s2x[N], s2y[N];
    __shared__ float u[NP1];          // row duals (1-based rows)
    __shared__ int   p[NP1];          // p[j] = row matched to column j (1-based), 0 = free
    __shared__ int   way[NP1];        // predecessor column on shortest path
    __shared__ float vinit[N];        // initial column duals
    __shared__ int   rowclaim[N];     // column that claims row i (min col wins)
    __shared__ int   freelist[N];     // free rows (1-based), in row order
    __shared__ unsigned warpmask[8];
    __shared__ int   snfree;
    __shared__ float swsum[8];

    const float* s1p = set1 + (size_t)b * N * 3;
    const float* s2p = set2 + (size_t)b * N * 10;

    s1x[tid] = s1p[tid * 3 + 0];
    s1y[tid] = s1p[tid * 3 + 1];
    s1l[tid] = s1p[tid * 3 + 2];
    s2x[tid] = s2p[tid * 10 + 0];
    s2y[tid] = s2p[tid * 10 + 1];
    u[tid]   = 0.0f;
    p[tid]   = 0;
    rowclaim[tid] = UNCLAIMED;
    if (tid == 0) { u[N] = 0.0f; p[N] = 0; }
    __syncthreads();

    // ---- Phase 1: column reduction. Thread tid owns column j = tid. ----
    {
        const float cx = s2x[tid];
        const float cy = s2y[tid];
        float bestd2 = BIGF;
        int   besti  = 0;
        #pragma unroll 4
        for (int i = 0; i < N; ++i) {
            const float dx = s1x[i] - cx;
            const float dy = s1y[i] - cy;
            const float d2 = fmaf(dx, dx, dy * dy);
            if (d2 < bestd2) { bestd2 = d2; besti = i; }
        }
        vinit[tid] = fsqrt_approx(fmaxf(bestd2, 0.0f));
        atomicMin(&rowclaim[besti], tid);   // deterministic: smallest column wins
        __syncthreads();
        if (rowclaim[besti] == tid) p[tid + 1] = besti + 1;   // claimed
        // Build ordered free-row list (rows = tid).
        const bool isfree = (rowclaim[tid] == UNCLAIMED);
        const unsigned wm = __ballot_sync(0xffffffffu, isfree);
        if (lane == 0) warpmask[wid] = wm;
        __syncthreads();
        int base = 0, tot = 0;
        #pragma unroll
        for (int w = 0; w < 8; ++w) {
            const int c = __popc(warpmask[w]);
            if (w < wid) base += c;
            tot += c;
        }
        if (isfree) freelist[base + __popc(wm & ((1u << lane) - 1u))] = tid + 1;
        if (tid == 0) snfree = tot;
        __syncthreads();
    }

    // ---- Phase 2: augmenting paths (warp 0 only). ----
    if (tid < 32) {
        const int nfree = snfree;
        float v[8], c2xr[8], c2yr[8];
        #pragma unroll
        for (int c = 0; c < 8; ++c) {
            const int col = lane + 32 * c;
            v[c]    = vinit[col];
            c2xr[c] = s2x[col];
            c2yr[c] = s2y[col];
        }

        for (int idx = 0; idx < nfree; ++idx) {
            const int ifree = freelist[idx];      // 1-based free row
            float dist[8], dmark[8];
            int   prow[8];
            unsigned usedm = 0;
            #pragma unroll
            for (int c = 0; c < 8; ++c) dist[c] = BIGF;

            int   j0   = 0;
            int   i0   = ifree;
            float u_i0 = u[i0];
            float D    = 0.0f;

            while (true) {
                // mark j0 used (owner lane), record mark distance & matched row
                if (j0 > 0) {
                    #pragma unroll
                    for (int c = 0; c < 8; ++c)
                        if (j0 == lane + 32 * c + 1) {
                            usedm |= (1u << c); dmark[c] = D; prow[c] = i0;
                        }
                }
                const float s1xi = s1x[i0 - 1];
                const float s1yi = s1y[i0 - 1];

                float bestv = BIGF;
                int   bestj = 0;
                #pragma unroll
                for (int c = 0; c < 8; ++c) {
                    if (!((usedm >> c) & 1u)) {
                        const float dx = s1xi - c2xr[c];
                        const float dy = s1yi - c2yr[c];
                        const float cost = fsqrt_approx(fmaf(dx, dx, dy * dy));
                        const float cand = D + fmaxf(cost - u_i0 - v[c], 0.0f);
                        if (cand < dist[c]) { dist[c] = cand; way[lane + 32 * c + 1] = j0; }
                        if (dist[c] < bestv) { bestv = dist[c]; bestj = lane + 32 * c + 1; }
                    }
                }
                // warp argmin: dist >= 0 so float bits are order-preserving as u32
                const unsigned ub = __float_as_uint(bestv);
                const unsigned m  = __reduce_min_sync(0xffffffffu, ub);
                const unsigned bl = __ballot_sync(0xffffffffu, ub == m);
                const int src = __ffs(bl) - 1;
                const int j1  = __shfl_sync(0xffffffffu, bestj, src);
                D = __uint_as_float(m);

                const int pj1 = p[j1];
                if (pj1 == 0) { j0 = j1; break; }
                j0 = j1; i0 = pj1; u_i0 = u[i0];
            }

            // deferred dual updates
            #pragma unroll
            for (int c = 0; c < 8; ++c) {
                if ((usedm >> c) & 1u) {
                    const float diff = D - dmark[c];
                    v[c] -= diff;
                    u[prow[c]] += diff;   // distinct rows -> race-free
                }
            }
            if (lane == 0) u[ifree] += D;
            __syncwarp();

            // augment along way chain (lane 0, serial)
            if (lane == 0) {
                int jj = j0;
                while (jj != 0) {
                    const int jp = way[jj];
                    p[jj] = (jp == 0) ? ifree : p[jp];
                    jj = jp;
                }
            }
            __syncwarp();
        }
    }
    __syncthreads();

    // ---- Phase 3: loss epilogue. Thread tid owns column c = tid. ----
    const int r = p[tid + 1] - 1;

    const float dx = s1x[r] - s2x[tid];
    const float dy = s1y[r] - s2y[tid];
    const float md = fsqrt_approx(fmaxf(fmaf(dx, dx, dy * dy), 0.0f));

    float lg[NUM_CLASSES];
    float mx = -1e30f;
    #pragma unroll
    for (int k = 0; k < NUM_CLASSES; ++k) {
        lg[k] = s2p[tid * 10 + 2 + k];
        mx = fmaxf(mx, lg[k]);
    }
    float se = 0.0f;
    #pragma unroll
    for (int k = 0; k < NUM_CLASSES; ++k) se += expf(lg[k] - mx);
    const float lse = mx + logf(se);

    const int  t    = (int)s1l[r];
    const bool mask = (t != -1);
    const int  st   = mask ? ((t < 0) ? 0 : (t >= NUM_CLASSES ? NUM_CLASSES - 1 : t)) : 0;
    const float nll = mask ? (lse - lg[st]) : 0.0f;
    const float cnt = mask ? 1.0f : 0.0f;

    float sv[3] = { md, nll, cnt };
    #pragma unroll
    for (int q = 0; q < 3; ++q) {
        float vv = sv[q];
        #pragma unroll
        for (int off = 16; off > 0; off >>= 1)
            vv += __shfl_down_sync(0xffffffffu, vv, off);
        if (lane == 0) swsum[wid] = vv;
        __syncthreads();
        if (tid == 0) {
            float s = 0.0f;
            #pragma unroll
            for (int w = 0; w < 8; ++w) s += swsum[w];
            sv[q] = s;
        }
        __syncthreads();
    }

    if (tid == 0) {
        const float loss1 = sv[0] / (float)N;
        const float denom = fmaxf(sv[2], 1.0f);
        const float loss2 = CE_COEFF * (sv[1] / denom);
        g_batch_loss[b] = loss1 + loss2;
    }
}

__global__ void finalize_kernel(float* __restrict__ out) {
    __shared__ float s[BATCH];
    const int t = threadIdx.x;
    s[t] = g_batch_loss[t];
    __syncthreads();
    #pragma unroll
    for (int off = BATCH / 2; off > 0; off >>= 1) {
        if (t < off) s[t] += s[t + off];
        __syncthreads();
    }
    if (t == 0) out[0] = s[0];
}

extern "C" void kernel_launch(void* const* d_in, const int* in_sizes, int n_in,
                              void* d_out, int out_size) {
    (void)in_sizes; (void)n_in; (void)out_size;
    const float* set1 = (const float*)d_in[0];
    const float* set2 = (const float*)d_in[1];
    float* out = (float*)d_out;

    hungarian_loss_kernel<<<BATCH, N>>>(set1, set2);
    finalize_kernel<<<1, BATCH>>>(out);
}

// round 3
// speedup vs baseline: 2.8329x; 2.8329x over previous
#include <cuda_runtime.h>
#include <math.h>

#define BATCH 128
#define N 256
#define NP1 (N + 1)
#define NUM_CLASSES 8
#define CE_COEFF 10.0f
#define UNCLAIMED 0x7FFFFFFF
#define BIGF 1e30f

__device__ float g_batch_loss[BATCH];

__device__ __forceinline__ float fsqrt_approx(float x) {
    float r;
    asm("sqrt.approx.f32 %0, %1;" : "=f"(r) : "f"(x));
    return r;
}

// One CTA per batch, 256 threads, thread tid owns column j = tid+1 (1-based).
// Phase 1: column-reduction init (v[j] = min_i cost, greedy row claim).
// Phase 2: exact shortest-augmenting-path for remaining free rows.
//          Absolute-distance Dijkstra, deferred dual updates, register-resident
//          per-column state, ONE __syncthreads per Dijkstra step (parity
//          double-buffered reduction), redundant cross-warp combine by all threads.
// Phase 3: fused loss epilogue.
__global__ __launch_bounds__(N, 1) void hungarian_loss_kernel(
    const float* __restrict__ set1,   // [B, N, 3]
    const float* __restrict__ set2)   // [B, N, 10]
{
    const int b    = blockIdx.x;
    const int tid  = threadIdx.x;
    const int lane = tid & 31;
    const int wid  = tid >> 5;
    const int j    = tid + 1;         // 1-based column id

    __shared__ float s1x[N], s1y[N], s1l[N];
    __shared__ float s2x[N], s2y[N];
    __shared__ float u[NP1];                   // row duals (1-based rows)
    __shared__ int   p[NP1];                   // p[j] = row matched to col j, 0 = free
    __shared__ int   way[NP1];                 // predecessor column on path
    __shared__ int   rowclaim[N];
    __shared__ int   freelist[N];
    __shared__ unsigned warpmask[8];
    __shared__ int   snfree;
    __shared__ unsigned long long red[2][8];   // packed (valbits<<32 | col), per warp
    __shared__ float swsum[8];

    const float* s1p = set1 + (size_t)b * N * 3;
    const float* s2p = set2 + (size_t)b * N * 10;

    s1x[tid] = s1p[tid * 3 + 0];
    s1y[tid] = s1p[tid * 3 + 1];
    s1l[tid] = s1p[tid * 3 + 2];
    s2x[tid] = s2p[tid * 10 + 0];
    s2y[tid] = s2p[tid * 10 + 1];
    u[tid]   = 0.0f;
    p[tid]   = 0;
    rowclaim[tid] = UNCLAIMED;
    if (tid == 0) { u[N] = 0.0f; p[N] = 0; }
    __syncthreads();

    const float c2x = s2x[tid];
    const float c2y = s2y[tid];
    float v;                          // column dual, register-resident

    // ---- Phase 1: column reduction ----
    {
        float bestd2 = BIGF;
        int   besti  = 0;
        #pragma unroll 4
        for (int i = 0; i < N; ++i) {
            const float dx = s1x[i] - c2x;
            const float dy = s1y[i] - c2y;
            const float d2 = fmaf(dx, dx, dy * dy);
            if (d2 < bestd2) { bestd2 = d2; besti = i; }
        }
        v = fsqrt_approx(fmaxf(bestd2, 0.0f));
        atomicMin(&rowclaim[besti], tid);       // deterministic: smallest col wins
        __syncthreads();
        if (rowclaim[besti] == tid) p[j] = besti + 1;
        const bool isfree = (rowclaim[tid] == UNCLAIMED);   // row = tid
        const unsigned wm = __ballot_sync(0xffffffffu, isfree);
        if (lane == 0) warpmask[wid] = wm;
        __syncthreads();
        int base = 0, tot = 0;
        #pragma unroll
        for (int w = 0; w < 8; ++w) {
            const int c = __popc(warpmask[w]);
            if (w < wid) base += c;
            tot += c;
        }
        if (isfree) freelist[base + __popc(wm & ((1u << lane) - 1u))] = tid + 1;
        if (tid == 0) snfree = tot;
        __syncthreads();
    }

    // ---- Phase 2: augmenting paths, all 256 threads ----
    const int nfree = snfree;
    for (int idx = 0; idx < nfree; ++idx) {
        const int ifree = freelist[idx];        // 1-based free row

        float dist  = BIGF;
        bool  used  = false;
        float dmark = 0.0f;
        int   prow  = 0;

        int   j1  = 0;                          // current scan-origin column (0 = virtual)
        int   i0  = ifree;                      // current scan row
        float u0  = u[i0];
        float D   = 0.0f;                       // distance of scan origin
        int   par = 0;

        while (true) {
            if (j == j1) { used = true; dmark = D; prow = i0; }

            const float s1xi = s1x[i0 - 1];
            const float s1yi = s1y[i0 - 1];
            unsigned mybits = 0xFFFFFFFFu;
            if (!used) {
                const float dx   = s1xi - c2x;
                const float dy   = s1yi - c2y;
                const float cost = fsqrt_approx(fmaf(dx, dx, dy * dy));
                const float cand = fmaxf((D - u0) + (cost - v), D);
                if (cand < dist) { dist = cand; way[j] = j1; }
                mybits = __float_as_uint(dist); // dist >= 0 -> bits order-preserving
            }

            // warp argmin (any tie ok: optimum generically unique)
            const unsigned m  = __reduce_min_sync(0xffffffffu, mybits);
            const unsigned bl = __ballot_sync(0xffffffffu, mybits == m);
            if (lane == 0)
                red[par][wid] = ((unsigned long long)m << 32) |
                                (unsigned)((wid << 5) + (__ffs(bl) - 1) + 1);
            __syncthreads();

            // all threads combine the 8 warp results
            unsigned long long bestp = red[par][0];
            #pragma unroll
            for (int w = 1; w < 8; ++w) {
                const unsigned long long o = red[par][w];
                if (o < bestp) bestp = o;
            }
            D  = __uint_as_float((unsigned)(bestp >> 32));
            j1 = (int)(bestp & 0xFFFFFFFFu);

            const int pj1 = p[j1];
            if (pj1 == 0) break;
            i0 = pj1;
            u0 = u[i0];
            par ^= 1;
        }

        // deferred dual updates (register v; u rows distinct across used columns)
        if (used) {
            const float diff = D - dmark;
            v -= diff;
            u[prow] += diff;
        }
        if (tid == 0) {
            u[ifree] += D;
            // augment along way chain
            int jj = j1;
            while (jj != 0) {
                const int jp = way[jj];
                p[jj] = (jp == 0) ? ifree : p[jp];
                jj = jp;
            }
        }
        __syncthreads();
    }

    // ---- Phase 3: loss epilogue. Thread tid owns column c = tid. ----
    const int r = p[j] - 1;

    const float dx = s1x[r] - c2x;
    const float dy = s1y[r] - c2y;
    const float md = fsqrt_approx(fmaxf(fmaf(dx, dx, dy * dy), 0.0f));

    float lg[NUM_CLASSES];
    float mx = -1e30f;
    #pragma unroll
    for (int k = 0; k < NUM_CLASSES; ++k) {
        lg[k] = s2p[tid * 10 + 2 + k];
        mx = fmaxf(mx, lg[k]);
    }
    float se = 0.0f;
    #pragma unroll
    for (int k = 0; k < NUM_CLASSES; ++k) se += expf(lg[k] - mx);
    const float lse = mx + logf(se);

    const int  t    = (int)s1l[r];
    const bool mask = (t != -1);
    const int  st   = mask ? ((t < 0) ? 0 : (t >= NUM_CLASSES ? NUM_CLASSES - 1 : t)) : 0;
    const float nll = mask ? (lse - lg[st]) : 0.0f;
    const float cnt = mask ? 1.0f : 0.0f;

    float sv[3] = { md, nll, cnt };
    #pragma unroll
    for (int q = 0; q < 3; ++q) {
        float vv = sv[q];
        #pragma unroll
        for (int off = 16; off > 0; off >>= 1)
            vv += __shfl_down_sync(0xffffffffu, vv, off);
        if (lane == 0) swsum[wid] = vv;
        __syncthreads();
        if (tid == 0) {
            float s = 0.0f;
            #pragma unroll
            for (int w = 0; w < 8; ++w) s += swsum[w];
            sv[q] = s;
        }
        __syncthreads();
    }

    if (tid == 0) {
        const float loss1 = sv[0] / (float)N;
        const float denom = fmaxf(sv[2], 1.0f);
        const float loss2 = CE_COEFF * (sv[1] / denom);
        g_batch_loss[b] = loss1 + loss2;
    }
}

__global__ void finalize_kernel(float* __restrict__ out) {
    __shared__ float s[BATCH];
    const int t = threadIdx.x;
    s[t] = g_batch_loss[t];
    __syncthreads();
    #pragma unroll
    for (int off = BATCH / 2; off > 0; off >>= 1) {
        if (t < off) s[t] += s[t + off];
        __syncthreads();
    }
    if (t == 0) out[0] = s[0];
}

extern "C" void kernel_launch(void* const* d_in, const int* in_sizes, int n_in,
                              void* d_out, int out_size) {
    (void)in_sizes; (void)n_in; (void)out_size;
    const float* set1 = (const float*)d_in[0];
    const float* set2 = (const float*)d_in[1];
    float* out = (float*)d_out;

    hungarian_loss_kernel<<<BATCH, N>>>(set1, set2);
    finalize_kernel<<<1, BATCH>>>(out);
}

// round 4
// speedup vs baseline: 3.1629x; 1.1165x over previous
#include <cuda_runtime.h>
#include <math.h>

#define BATCH 128
#define N 256
#define NP1 (N + 1)
#define NUM_CLASSES 8
#define CE_COEFF 10.0f
#define UNCLAIMED 0x7FFFFFFF
#define BIGF 1e30f

__device__ float g_batch_loss[BATCH];

__device__ __forceinline__ float fsqrt_approx(float x) {
    float r;
    asm("sqrt.approx.f32 %0, %1;" : "=f"(r) : "f"(x));
    return r;
}

// One CTA per batch, 256 threads, thread tid owns column j = tid+1 (1-based).
// Phase 1 : column-reduction init (v[j] = min_i cost, greedy row claim).
// Phase 1.5: JV augmenting row reduction, 2 passes (assigns most remaining rows,
//            tightens duals; feasibility preserved => later phase stays exact).
// Phase 2 : exact shortest-augmenting-path for remaining free rows.
// Phase 3 : fused loss epilogue.
__global__ __launch_bounds__(N, 1) void hungarian_loss_kernel(
    const float* __restrict__ set1,   // [B, N, 3]
    const float* __restrict__ set2)   // [B, N, 10]
{
    const int b    = blockIdx.x;
    const int tid  = threadIdx.x;
    const int lane = tid & 31;
    const int wid  = tid >> 5;
    const int j    = tid + 1;         // 1-based column id

    __shared__ float s1x[N], s1y[N], s1l[N];
    __shared__ float s2x[N], s2y[N];
    __shared__ float u[NP1];                   // row duals (1-based rows)
    __shared__ int   p[NP1];                   // p[j] = row matched to col j, 0 = free
    __shared__ int   way[NP1];                 // predecessor column on path
    __shared__ int   rowclaim[N];
    __shared__ int   listA[N], listB[N];
    __shared__ unsigned warpmask[8];
    __shared__ int   snfree, snext;
    __shared__ unsigned long long red[2][8];   // packed (valbits<<32 | col), per warp
    __shared__ unsigned red2[2][8];            // per-warp second-min bits
    __shared__ float swsum[8];

    const float* s1p = set1 + (size_t)b * N * 3;
    const float* s2p = set2 + (size_t)b * N * 10;

    s1x[tid] = s1p[tid * 3 + 0];
    s1y[tid] = s1p[tid * 3 + 1];
    s1l[tid] = s1p[tid * 3 + 2];
    s2x[tid] = s2p[tid * 10 + 0];
    s2y[tid] = s2p[tid * 10 + 1];
    u[tid]   = 0.0f;
    p[tid]   = 0;
    rowclaim[tid] = UNCLAIMED;
    if (tid == 0) { u[N] = 0.0f; p[N] = 0; }
    __syncthreads();

    const float c2x = s2x[tid];
    const float c2y = s2y[tid];
    float v;                          // column dual, register-resident

    // ---- Phase 1: column reduction ----
    {
        float bestd2 = BIGF;
        int   besti  = 0;
        #pragma unroll 4
        for (int i = 0; i < N; ++i) {
            const float dx = s1x[i] - c2x;
            const float dy = s1y[i] - c2y;
            const float d2 = fmaf(dx, dx, dy * dy);
            if (d2 < bestd2) { bestd2 = d2; besti = i; }
        }
        v = fsqrt_approx(fmaxf(bestd2, 0.0f));
        atomicMin(&rowclaim[besti], tid);       // deterministic: smallest col wins
        __syncthreads();
        if (rowclaim[besti] == tid) p[j] = besti + 1;
        const bool isfree = (rowclaim[tid] == UNCLAIMED);   // row = tid
        const unsigned wm = __ballot_sync(0xffffffffu, isfree);
        if (lane == 0) warpmask[wid] = wm;
        __syncthreads();
        int base = 0, tot = 0;
        #pragma unroll
        for (int w = 0; w < 8; ++w) {
            const int c = __popc(warpmask[w]);
            if (w < wid) base += c;
            tot += c;
        }
        if (isfree) listA[base + __popc(wm & ((1u << lane) - 1u))] = tid + 1;
        if (tid == 0) snfree = tot;
        __syncthreads();
    }

    // ---- Phase 1.5: augmenting row reduction (2 passes) ----
    int ncur = snfree;
    {
        int par = 0;
        for (int run = 0; run < 2; ++run) {
            int* cur = (run == 0) ? listA : listB;
            int* nxt = (run == 0) ? listB : listA;
            if (tid == 0) snext = 0;
            __syncthreads();
            for (int t = 0; t < ncur; ++t) {
                const int i = cur[t];
                const float dx = s1x[i - 1] - c2x;
                const float dy = s1y[i - 1] - c2y;
                const float rc = fmaxf(fsqrt_approx(fmaf(dx, dx, dy * dy)) - v, 0.0f);
                const unsigned bits = __float_as_uint(rc);
                const unsigned m1w  = __reduce_min_sync(0xffffffffu, bits);
                const unsigned bl   = __ballot_sync(0xffffffffu, bits == m1w);
                const int leader    = __ffs(bl) - 1;
                const unsigned bits2 = (lane == leader) ? 0xFFFFFFFFu : bits;
                const unsigned m2w  = __reduce_min_sync(0xffffffffu, bits2);
                if (lane == 0) {
                    red[par][wid]  = ((unsigned long long)m1w << 32) |
                                     (unsigned)((wid << 5) + leader + 1);
                    red2[par][wid] = m2w;
                }
                __syncthreads();
                unsigned long long bp = red[par][0];
                #pragma unroll
                for (int w = 1; w < 8; ++w) {
                    const unsigned long long o = red[par][w];
                    if (o < bp) bp = o;
                }
                unsigned sec = 0xFFFFFFFFu;
                #pragma unroll
                for (int w = 0; w < 8; ++w) {
                    const unsigned long long o = red[par][w];
                    const unsigned cand = (o == bp) ? red2[par][w] : (unsigned)(o >> 32);
                    if (cand < sec) sec = cand;
                }
                const float m1   = __uint_as_float((unsigned)(bp >> 32));
                const int   jone = (int)(bp & 0xFFFFFFFFu);
                const float m2   = __uint_as_float(sec);
                if (tid == jone - 1) {            // owner handles all updates (no races)
                    if (m1 < m2) {
                        v -= (m2 - m1);
                        const int k = p[jone];
                        p[jone] = i;
                        u[i] = m2;
                        if (k != 0) { nxt[snext] = k; snext = snext + 1; }
                    } else {                      // exact tie (rare)
                        if (p[jone] == 0) { p[jone] = i; u[i] = m2; }
                        else { nxt[snext] = i; snext = snext + 1; }
                    }
                }
                par ^= 1;
            }
            __syncthreads();
            ncur = snext;
            __syncthreads();
        }
    }
    // remaining free rows now in listA[0..ncur)

    // ---- Phase 2: augmenting paths, all 256 threads ----
    for (int idx = 0; idx < ncur; ++idx) {
        const int ifree = listA[idx];           // 1-based free row

        float dist  = BIGF;
        bool  used  = false;
        float dmark = 0.0f;
        int   prow  = 0;

        int   j1  = 0;                          // current scan-origin column (0 = virtual)
        int   i0  = ifree;                      // current scan row
        float u0  = u[i0];
        float D   = 0.0f;                       // distance of scan origin
        int   par = 0;

        while (true) {
            if (j == j1) { used = true; dmark = D; prow = i0; }

            const float s1xi = s1x[i0 - 1];
            const float s1yi = s1y[i0 - 1];
            unsigned mybits = 0xFFFFFFFFu;
            if (!used) {
                const float dx   = s1xi - c2x;
                const float dy   = s1yi - c2y;
                const float cost = fsqrt_approx(fmaf(dx, dx, dy * dy));
                const float cand = fmaxf((D - u0) + (cost - v), D);
                if (cand < dist) { dist = cand; way[j] = j1; }
                mybits = __float_as_uint(dist); // dist >= 0 -> bits order-preserving
            }

            const unsigned m  = __reduce_min_sync(0xffffffffu, mybits);
            const unsigned bl = __ballot_sync(0xffffffffu, mybits == m);
            if (lane == 0)
                red[par][wid] = ((unsigned long long)m << 32) |
                                (unsigned)((wid << 5) + (__ffs(bl) - 1) + 1);
            __syncthreads();

            unsigned long long bestp = red[par][0];
            #pragma unroll
            for (int w = 1; w < 8; ++w) {
                const unsigned long long o = red[par][w];
                if (o < bestp) bestp = o;
            }
            D  = __uint_as_float((unsigned)(bestp >> 32));
            j1 = (int)(bestp & 0xFFFFFFFFu);

            const int pj1 = p[j1];
            if (pj1 == 0) break;
            i0 = pj1;
            u0 = u[i0];
            par ^= 1;
        }

        // deferred dual updates (register v; u rows distinct across used columns)
        if (used) {
            const float diff = D - dmark;
            v -= diff;
            u[prow] += diff;
        }
        if (tid == 0) {
            u[ifree] += D;
            int jj = j1;
            while (jj != 0) {
                const int jp = way[jj];
                p[jj] = (jp == 0) ? ifree : p[jp];
                jj = jp;
            }
        }
        __syncthreads();
    }

    // ---- Phase 3: loss epilogue. Thread tid owns column c = tid. ----
    const int r = p[j] - 1;

    const float dxm = s1x[r] - c2x;
    const float dym = s1y[r] - c2y;
    const float md = fsqrt_approx(fmaxf(fmaf(dxm, dxm, dym * dym), 0.0f));

    float lg[NUM_CLASSES];
    float mx = -1e30f;
    #pragma unroll
    for (int k = 0; k < NUM_CLASSES; ++k) {
        lg[k] = s2p[tid * 10 + 2 + k];
        mx = fmaxf(mx, lg[k]);
    }
    float se = 0.0f;
    #pragma unroll
    for (int k = 0; k < NUM_CLASSES; ++k) se += expf(lg[k] - mx);
    const float lse = mx + logf(se);

    const int  t    = (int)s1l[r];
    const bool mask = (t != -1);
    const int  st   = mask ? ((t < 0) ? 0 : (t >= NUM_CLASSES ? NUM_CLASSES - 1 : t)) : 0;
    const float nll = mask ? (lse - lg[st]) : 0.0f;
    const float cnt = mask ? 1.0f : 0.0f;

    float sv[3] = { md, nll, cnt };
    #pragma unroll
    for (int q = 0; q < 3; ++q) {
        float vv = sv[q];
        #pragma unroll
        for (int off = 16; off > 0; off >>= 1)
            vv += __shfl_down_sync(0xffffffffu, vv, off);
        if (lane == 0) swsum[wid] = vv;
        __syncthreads();
        if (tid == 0) {
            float s = 0.0f;
            #pragma unroll
            for (int w = 0; w < 8; ++w) s += swsum[w];
            sv[q] = s;
        }
        __syncthreads();
    }

    if (tid == 0) {
        const float loss1 = sv[0] / (float)N;
        const float denom = fmaxf(sv[2], 1.0f);
        const float loss2 = CE_COEFF * (sv[1] / denom);
        g_batch_loss[b] = loss1 + loss2;
    }
}

__global__ void finalize_kernel(float* __restrict__ out) {
    __shared__ float s[BATCH];
    const int t = threadIdx.x;
    s[t] = g_batch_loss[t];
    __syncthreads();
    #pragma unroll
    for (int off = BATCH / 2; off > 0; off >>= 1) {
        if (t < off) s[t] += s[t + off];
        __syncthreads();
    }
    if (t == 0) out[0] = s[0];
}

extern "C" void kernel_launch(void* const* d_in, const int* in_sizes, int n_in,
                              void* d_out, int out_size) {
    (void)in_sizes; (void)n_in; (void)out_size;
    const float* set1 = (const float*)d_in[0];
    const float* set2 = (const float*)d_in[1];
    float* out = (float*)d_out;

    hungarian_loss_kernel<<<BATCH, N>>>(set1, set2);
    finalize_kernel<<<1, BATCH>>>(out);
}

// round 5
// speedup vs baseline: 4.5508x; 1.4388x over previous
#include <cuda_runtime.h>
#include <math.h>

#define BATCH 128
#define N 256
#define NP1 (N + 1)
#define NUM_CLASSES 8
#define CE_COEFF 10.0f
#define UNCLAIMED 0x7FFFFFFF
#define BIGF 1e30f
#define VMASK 0xFFFFFF00u

__device__ float g_batch_loss[BATCH];

__device__ __forceinline__ float fsqrt_approx(float x) {
    float r;
    asm("sqrt.approx.f32 %0, %1;" : "=f"(r) : "f"(x));
    return r;
}
__device__ __forceinline__ unsigned umin2(unsigned a, unsigned b) { return a < b ? a : b; }

// One CTA per batch, 256 threads, thread tid owns column j = tid+1 (1-based).
// Phase 1  : column reduction (v[j] = min_i cost, greedy row claim).
// Phase 1.5: JV augmenting row reduction (2 passes), packed-REDUX argmin.
// Phase 2  : exact shortest-augmenting-path; packed argmin (col in low 8 bits
//            of float bits), fused (row, u[row]) lookup table, 1 barrier/step.
// Phase 3  : fused loss epilogue.
__global__ __launch_bounds__(N, 1) void hungarian_loss_kernel(
    const float* __restrict__ set1,   // [B, N, 3]
    const float* __restrict__ set2)   // [B, N, 10]
{
    const int b    = blockIdx.x;
    const int tid  = threadIdx.x;
    const int lane = tid & 31;
    const int wid  = tid >> 5;
    const int j    = tid + 1;         // 1-based column id

    __shared__ float s1x[N], s1y[N], s1l[N];
    __shared__ float s2x[N], s2y[N];
    __shared__ float u[NP1];                    // row duals (1-based rows)
    __shared__ int2  pu[NP1];                   // pu[j] = {row p[j], bits(u[p[j]])}
    __shared__ int   way[NP1];                  // predecessor column on path
    __shared__ int   rowclaim[N];
    __shared__ int   listA[N], listB[N];
    __shared__ unsigned warpmask[8];
    __shared__ int   snfree, snext;
    __shared__ __align__(16) unsigned red1[2][8];
    __shared__ __align__(16) unsigned red2s[2][8];
    __shared__ float swsum[8];

    const float* s1p = set1 + (size_t)b * N * 3;
    const float* s2p = set2 + (size_t)b * N * 10;

    s1x[tid] = s1p[tid * 3 + 0];
    s1y[tid] = s1p[tid * 3 + 1];
    s1l[tid] = s1p[tid * 3 + 2];
    s2x[tid] = s2p[tid * 10 + 0];
    s2y[tid] = s2p[tid * 10 + 1];
    u[tid]   = 0.0f;
    pu[tid]  = make_int2(0, 0);
    rowclaim[tid] = UNCLAIMED;
    if (tid == 0) { u[N] = 0.0f; pu[N] = make_int2(0, 0); }
    __syncthreads();

    const float c2x = s2x[tid];
    const float c2y = s2y[tid];
    float v;                          // column dual, register-resident

    // ---- Phase 1: column reduction ----
    {
        float bestd2 = BIGF;
        int   besti  = 0;
        #pragma unroll 4
        for (int i = 0; i < N; ++i) {
            const float dx = s1x[i] - c2x;
            const float dy = s1y[i] - c2y;
            const float d2 = fmaf(dx, dx, dy * dy);
            if (d2 < bestd2) { bestd2 = d2; besti = i; }
        }
        v = fsqrt_approx(fmaxf(bestd2, 0.0f));
        atomicMin(&rowclaim[besti], tid);       // deterministic: smallest col wins
        __syncthreads();
        if (rowclaim[besti] == tid) pu[j] = make_int2(besti + 1, 0);
        const bool isfree = (rowclaim[tid] == UNCLAIMED);   // row = tid
        const unsigned wm = __ballot_sync(0xffffffffu, isfree);
        if (lane == 0) warpmask[wid] = wm;
        __syncthreads();
        int base = 0, tot = 0;
        #pragma unroll
        for (int w = 0; w < 8; ++w) {
            const int c = __popc(warpmask[w]);
            if (w < wid) base += c;
            tot += c;
        }
        if (isfree) listA[base + __popc(wm & ((1u << lane) - 1u))] = tid + 1;
        if (tid == 0) snfree = tot;
        __syncthreads();
    }

    // ---- Phase 1.5: augmenting row reduction (2 passes) ----
    int ncur = snfree;
    {
        int par = 0;
        for (int run = 0; run < 2; ++run) {
            int* cur = (run == 0) ? listA : listB;
            int* nxt = (run == 0) ? listB : listA;
            if (tid == 0) snext = 0;
            __syncthreads();
            for (int t = 0; t < ncur; ++t) {
                const int i = cur[t];
                const float dx = s1x[i - 1] - c2x;
                const float dy = s1y[i - 1] - c2y;
                const float rc = fmaxf(fsqrt_approx(fmaf(dx, dx, dy * dy)) - v, 0.0f);
                const unsigned bits = (__float_as_uint(rc) & VMASK) | (unsigned)tid;
                const unsigned m1w  = __reduce_min_sync(0xffffffffu, bits);
                const unsigned b2   = (bits == m1w) ? 0xFFFFFFFFu : bits;
                const unsigned m2w  = __reduce_min_sync(0xffffffffu, b2);
                if (lane == 0) { red1[par][wid] = m1w; red2s[par][wid] = m2w; }
                __syncthreads();
                unsigned bp = red1[par][0];
                #pragma unroll
                for (int w = 1; w < 8; ++w) bp = umin2(bp, red1[par][w]);
                unsigned sec = 0xFFFFFFFFu;
                #pragma unroll
                for (int w = 0; w < 8; ++w) {
                    const unsigned o = red1[par][w];
                    sec = umin2(sec, (o == bp) ? red2s[par][w] : o);
                }
                const int   jone = (int)(bp & 0xFFu) + 1;
                const float m1   = __uint_as_float(bp & VMASK);
                const float m2   = __uint_as_float(sec & VMASK);
                if (tid == jone - 1) {            // owner handles all updates (no races)
                    if (m1 < m2) {
                        v -= (m2 - m1);
                        const int k = pu[jone].x;
                        pu[jone] = make_int2(i, __float_as_int(m2));
                        u[i] = m2;
                        if (k != 0) { nxt[snext] = k; snext = snext + 1; }
                    } else {                      // truncation tie (rare)
                        if (pu[jone].x == 0) { pu[jone] = make_int2(i, __float_as_int(m2)); u[i] = m2; }
                        else { nxt[snext] = i; snext = snext + 1; }
                    }
                }
                par ^= 1;
            }
            __syncthreads();
            ncur = snext;
            __syncthreads();
        }
    }
    // remaining free rows now in listA[0..ncur)

    // ---- Phase 2: augmenting paths, all 256 threads ----
    for (int idx = 0; idx < ncur; ++idx) {
        const int ifree = listA[idx];           // 1-based free row

        float dist  = BIGF;
        bool  used  = false;
        float dmark = 0.0f;
        int   prow  = 0;

        int   jcur = 0;                         // scan-origin column (0 = virtual)
        int   jfin;                             // final free column
        int   i0   = ifree;
        float u0   = u[i0];
        float D    = 0.0f;
        int   par  = 0;

        while (true) {
            if (j == jcur) { used = true; dmark = D; prow = i0; }

            const float s1xi = s1x[i0 - 1];
            const float s1yi = s1y[i0 - 1];
            unsigned mybits = 0xFFFFFFFFu;
            if (!used) {
                const float dx   = s1xi - c2x;
                const float dy   = s1yi - c2y;
                const float cost = fsqrt_approx(fmaf(dx, dx, dy * dy));
                const float cand = fmaxf((D - u0) + (cost - v), D);
                if (cand < dist) { dist = cand; way[j] = jcur; }
                mybits = (__float_as_uint(dist) & VMASK) | (unsigned)tid;
            }

            const unsigned m = __reduce_min_sync(0xffffffffu, mybits);
            if (lane == 0) red1[par][wid] = m;
            __syncthreads();

            const uint4* rp = (const uint4*)&red1[par][0];
            const uint4 a = rp[0], c = rp[1];
            unsigned best = umin2(umin2(umin2(a.x, a.y), umin2(a.z, a.w)),
                                  umin2(umin2(c.x, c.y), umin2(c.z, c.w)));
            D    = __uint_as_float(best & VMASK);
            const int jn = (int)(best & 0xFFu) + 1;

            const int2 pj = pu[jn];
            if (pj.x == 0) { jfin = jn; break; }
            jcur = jn;
            i0   = pj.x;
            u0   = __uint_as_float((unsigned)pj.y);
            par ^= 1;
        }

        // deferred dual updates (owners), then augment chain (tid 0)
        if (used) {
            const float diff = D - dmark;
            v -= diff;
            u[prow] += diff;
            pu[j].y = __float_as_int(__uint_as_float((unsigned)pu[j].y) + diff);
        }
        if (tid == 0) u[ifree] += D;
        __syncthreads();
        if (tid == 0) {
            int jj = jfin;
            while (jj != 0) {
                const int jp = way[jj];
                const int nr = (jp == 0) ? ifree : pu[jp].x;
                pu[jj] = make_int2(nr, __float_as_int(u[nr]));
                jj = jp;
            }
        }
        __syncthreads();
    }

    // ---- Phase 3: loss epilogue. Thread tid owns column c = tid. ----
    const int r = pu[j].x - 1;

    const float dxm = s1x[r] - c2x;
    const float dym = s1y[r] - c2y;
    const float md = fsqrt_approx(fmaxf(fmaf(dxm, dxm, dym * dym), 0.0f));

    float lg[NUM_CLASSES];
    float mx = -1e30f;
    #pragma unroll
    for (int k = 0; k < NUM_CLASSES; ++k) {
        lg[k] = s2p[tid * 10 + 2 + k];
        mx = fmaxf(mx, lg[k]);
    }
    float se = 0.0f;
    #pragma unroll
    for (int k = 0; k < NUM_CLASSES; ++k) se += expf(lg[k] - mx);
    const float lse = mx + logf(se);

    const int  t    = (int)s1l[r];
    const bool mask = (t != -1);
    const int  st   = mask ? ((t < 0) ? 0 : (t >= NUM_CLASSES ? NUM_CLASSES - 1 : t)) : 0;
    const float nll = mask ? (lse - lg[st]) : 0.0f;
    const float cnt = mask ? 1.0f : 0.0f;

    float sv[3] = { md, nll, cnt };
    #pragma unroll
    for (int q = 0; q < 3; ++q) {
        float vv = sv[q];
        #pragma unroll
        for (int off = 16; off > 0; off >>= 1)
            vv += __shfl_down_sync(0xffffffffu, vv, off);
        if (lane == 0) swsum[wid] = vv;
        __syncthreads();
        if (tid == 0) {
            float s = 0.0f;
            #pragma unroll
            for (int w = 0; w < 8; ++w) s += swsum[w];
            sv[q] = s;
        }
        __syncthreads();
    }

    if (tid == 0) {
        const float loss1 = sv[0] / (float)N;
        const float denom = fmaxf(sv[2], 1.0f);
        const float loss2 = CE_COEFF * (sv[1] / denom);
        g_batch_loss[b] = loss1 + loss2;
    }
}

__global__ void finalize_kernel(float* __restrict__ out) {
    __shared__ float s[BATCH];
    const int t = threadIdx.x;
    s[t] = g_batch_loss[t];
    __syncthreads();
    #pragma unroll
    for (int off = BATCH / 2; off > 0; off >>= 1) {
        if (t < off) s[t] += s[t + off];
        __syncthreads();
    }
    if (t == 0) out[0] = s[0];
}

extern "C" void kernel_launch(void* const* d_in, const int* in_sizes, int n_in,
                              void* d_out, int out_size) {
    (void)in_sizes; (void)n_in; (void)out_size;
    const float* set1 = (const float*)d_in[0];
    const float* set2 = (const float*)d_in[1];
    float* out = (float*)d_out;

    hungarian_loss_kernel<<<BATCH, N>>>(set1, set2);
    finalize_kernel<<<1, BATCH>>>(out);
}

// round 6
// speedup vs baseline: 4.8280x; 1.0609x over previous
#include <cuda_runtime.h>
#include <math.h>

#define BATCH 128
#define N 256
#define NP1 (N + 1)
#define NUM_CLASSES 8
#define CE_COEFF 10.0f
#define UNCLAIMED 0x7FFFFFFF
#define BIGF 1e30f
#define VMASK 0xFFFFFF00u

__device__ float g_batch_loss[BATCH];

__device__ __forceinline__ float fsqrt_approx(float x) {
    float r;
    asm("sqrt.approx.f32 %0, %1;" : "=f"(r) : "f"(x));
    return r;
}
__device__ __forceinline__ unsigned umin2(unsigned a, unsigned b) { return a < b ? a : b; }

// One CTA per batch, 256 threads, thread tid owns column j = tid+1 (1-based).
// Phase 1  : column reduction (v[j] = min_i cost, greedy row claim).
// Phase 1.5: JV augmenting row reduction (2 passes), packed-REDUX argmin.
// Phase 2  : exact shortest-augmenting-path; packed argmin, fused per-column
//            row table rowdat[j] = {x, y, u, row} (one LDS.128 per step).
// Phase 3  : fused loss epilogue.
__global__ __launch_bounds__(N, 1) void hungarian_loss_kernel(
    const float* __restrict__ set1,   // [B, N, 3]
    const float* __restrict__ set2)   // [B, N, 10]
{
    const int b    = blockIdx.x;
    const int tid  = threadIdx.x;
    const int lane = tid & 31;
    const int wid  = tid >> 5;
    const int j    = tid + 1;         // 1-based column id

    __shared__ float s1x[N], s1y[N], s1l[N];
    __shared__ float s2x[N], s2y[N];
    __shared__ float u[NP1];                    // row duals (1-based rows)
    __shared__ __align__(16) float4 rowdat[NP1]; // per column j: {x,y,u,row} of p[j]
    __shared__ int   way[NP1];                  // predecessor column on path
    __shared__ int   rowclaim[N];
    __shared__ int   listA[N], listB[N];
    __shared__ unsigned warpmask[8];
    __shared__ int   snfree, snext;
    __shared__ __align__(16) unsigned red1[2][8];
    __shared__ __align__(16) unsigned red2s[2][8];
    __shared__ float swsum[8];

    const float* s1p = set1 + (size_t)b * N * 3;
    const float* s2p = set2 + (size_t)b * N * 10;

    s1x[tid] = s1p[tid * 3 + 0];
    s1y[tid] = s1p[tid * 3 + 1];
    s1l[tid] = s1p[tid * 3 + 2];
    s2x[tid] = s2p[tid * 10 + 0];
    s2y[tid] = s2p[tid * 10 + 1];
    u[tid]   = 0.0f;
    rowdat[tid] = make_float4(0.f, 0.f, 0.f, __int_as_float(0));
    rowclaim[tid] = UNCLAIMED;
    if (tid == 0) { u[N] = 0.0f; rowdat[N] = make_float4(0.f, 0.f, 0.f, __int_as_float(0)); }
    __syncthreads();

    const float c2x = s2x[tid];
    const float c2y = s2y[tid];
    float v;                          // column dual, register-resident

    // ---- Phase 1: column reduction ----
    {
        float bestd2 = BIGF;
        int   besti  = 0;
        #pragma unroll 4
        for (int i = 0; i < N; ++i) {
            const float dx = s1x[i] - c2x;
            const float dy = s1y[i] - c2y;
            const float d2 = fmaf(dx, dx, dy * dy);
            if (d2 < bestd2) { bestd2 = d2; besti = i; }
        }
        v = fsqrt_approx(fmaxf(bestd2, 0.0f));
        atomicMin(&rowclaim[besti], tid);       // deterministic: smallest col wins
        __syncthreads();
        if (rowclaim[besti] == tid)
            rowdat[j] = make_float4(s1x[besti], s1y[besti], 0.0f, __int_as_float(besti + 1));
        const bool isfree = (rowclaim[tid] == UNCLAIMED);   // row = tid
        const unsigned wm = __ballot_sync(0xffffffffu, isfree);
        if (lane == 0) warpmask[wid] = wm;
        __syncthreads();
        int base = 0, tot = 0;
        #pragma unroll
        for (int w = 0; w < 8; ++w) {
            const int c = __popc(warpmask[w]);
            if (w < wid) base += c;
            tot += c;
        }
        if (isfree) listA[base + __popc(wm & ((1u << lane) - 1u))] = tid + 1;
        if (tid == 0) snfree = tot;
        __syncthreads();
    }

    // ---- Phase 1.5: augmenting row reduction (2 passes) ----
    int ncur = snfree;
    {
        int par = 0;
        for (int run = 0; run < 2; ++run) {
            int* cur = (run == 0) ? listA : listB;
            int* nxt = (run == 0) ? listB : listA;
            if (tid == 0) snext = 0;
            __syncthreads();
            for (int t = 0; t < ncur; ++t) {
                const int i = cur[t];
                const float dx = s1x[i - 1] - c2x;
                const float dy = s1y[i - 1] - c2y;
                const float rc = fmaxf(fsqrt_approx(fmaf(dx, dx, dy * dy)) - v, 0.0f);
                const unsigned bits = (__float_as_uint(rc) & VMASK) | (unsigned)tid;
                const unsigned m1w  = __reduce_min_sync(0xffffffffu, bits);
                const unsigned b2   = (bits == m1w) ? 0xFFFFFFFFu : bits;
                const unsigned m2w  = __reduce_min_sync(0xffffffffu, b2);
                if (lane == 0) { red1[par][wid] = m1w; red2s[par][wid] = m2w; }
                __syncthreads();
                unsigned bp = red1[par][0];
                #pragma unroll
                for (int w = 1; w < 8; ++w) bp = umin2(bp, red1[par][w]);
                unsigned sec = 0xFFFFFFFFu;
                #pragma unroll
                for (int w = 0; w < 8; ++w) {
                    const unsigned o = red1[par][w];
                    sec = umin2(sec, (o == bp) ? red2s[par][w] : o);
                }
                const int   jone = (int)(bp & 0xFFu) + 1;
                const float m1   = __uint_as_float(bp & VMASK);
                const float m2   = __uint_as_float(sec & VMASK);
                if (tid == jone - 1) {            // owner handles all updates (no races)
                    const int k = __float_as_int(rowdat[jone].w);
                    if (m1 < m2) {
                        v -= (m2 - m1);
                        rowdat[jone] = make_float4(s1x[i - 1], s1y[i - 1], m2, __int_as_float(i));
                        u[i] = m2;
                        if (k != 0) { nxt[snext] = k; snext = snext + 1; }
                    } else {                      // truncation tie (rare)
                        if (k == 0) {
                            rowdat[jone] = make_float4(s1x[i - 1], s1y[i - 1], m2, __int_as_float(i));
                            u[i] = m2;
                        } else { nxt[snext] = i; snext = snext + 1; }
                    }
                }
                par ^= 1;
            }
            __syncthreads();
            ncur = snext;
            __syncthreads();
        }
    }
    // remaining free rows now in listA[0..ncur)

    // ---- Phase 2: augmenting paths, all 256 threads ----
    for (int idx = 0; idx < ncur; ++idx) {
        const int ifree = listA[idx];           // 1-based free row

        unsigned distbits = 0xFFFFFFFFu;        // packed (distbits&VMASK)|tid
        bool  used  = false;
        float dmark = 0.0f;
        int   prow  = 0;

        int   jcur = 0;                         // scan-origin column (0 = virtual)
        int   jfin;                             // final free column
        int   i0   = ifree;
        float rx   = s1x[ifree - 1];
        float ry   = s1y[ifree - 1];
        float u0   = u[ifree];
        float D    = 0.0f;
        int   par  = 0;

        while (true) {
            if (j == jcur) { used = true; dmark = D; prow = i0; }

            unsigned mybits = 0xFFFFFFFFu;
            if (!used) {
                const float dx   = rx - c2x;
                const float dy   = ry - c2y;
                const float cost = fsqrt_approx(fmaf(dx, dx, dy * dy));
                const float cand = fmaxf((D - u0) + (cost - v), D);
                const unsigned cb = (__float_as_uint(cand) & VMASK) | (unsigned)tid;
                if (cb < distbits) { distbits = cb; way[j] = jcur; }
                mybits = distbits;
            }

            const unsigned m = __reduce_min_sync(0xffffffffu, mybits);
            if (lane == 0) red1[par][wid] = m;
            __syncthreads();

            const uint4* rp = (const uint4*)&red1[par][0];
            const uint4 a = rp[0], c = rp[1];
            unsigned best = umin2(umin2(umin2(a.x, a.y), umin2(a.z, a.w)),
                                  umin2(umin2(c.x, c.y), umin2(c.z, c.w)));
            D = __uint_as_float(best & VMASK);
            const int jn = (int)(best & 0xFFu) + 1;

            const float4 rd = rowdat[jn];
            const int pj = __float_as_int(rd.w);
            if (pj == 0) { jfin = jn; break; }
            jcur = jn;
            i0   = pj;
            rx   = rd.x;
            ry   = rd.y;
            u0   = rd.z;
            par ^= 1;
        }

        // deferred dual updates (owners), then augment chain (tid 0)
        if (used) {
            const float diff = D - dmark;
            v -= diff;
            u[prow] += diff;
            rowdat[j].z += diff;
        }
        if (tid == 0) u[ifree] += D;
        __syncthreads();
        if (tid == 0) {
            int jj = jfin;
            while (jj != 0) {
                const int jp = way[jj];
                if (jp == 0) {
                    rowdat[jj] = make_float4(s1x[ifree - 1], s1y[ifree - 1],
                                             u[ifree], __int_as_float(ifree));
                } else {
                    rowdat[jj] = rowdat[jp];    // column jj inherits jp's old row (+dual)
                }
                jj = jp;
            }
        }
        __syncthreads();
    }

    // ---- Phase 3: loss epilogue. Thread tid owns column c = tid. ----
    const float4 rdf = rowdat[j];
    const int r = __float_as_int(rdf.w) - 1;

    const float dxm = rdf.x - c2x;
    const float dym = rdf.y - c2y;
    const float md = fsqrt_approx(fmaxf(fmaf(dxm, dxm, dym * dym), 0.0f));

    float lg[NUM_CLASSES];
    float mx = -1e30f;
    #pragma unroll
    for (int k = 0; k < NUM_CLASSES; ++k) {
        lg[k] = s2p[tid * 10 + 2 + k];
        mx = fmaxf(mx, lg[k]);
    }
    float se = 0.0f;
    #pragma unroll
    for (int k = 0; k < NUM_CLASSES; ++k) se += expf(lg[k] - mx);
    const float lse = mx + logf(se);

    const int  t    = (int)s1l[r];
    const bool mask = (t != -1);
    const int  st   = mask ? ((t < 0) ? 0 : (t >= NUM_CLASSES ? NUM_CLASSES - 1 : t)) : 0;
    const float nll = mask ? (lse - lg[st]) : 0.0f;
    const float cnt = mask ? 1.0f : 0.0f;

    float sv[3] = { md, nll, cnt };
    #pragma unroll
    for (int q = 0; q < 3; ++q) {
        float vv = sv[q];
        #pragma unroll
        for (int off = 16; off > 0; off >>= 1)
            vv += __shfl_down_sync(0xffffffffu, vv, off);
        if (lane == 0) swsum[wid] = vv;
        __syncthreads();
        if (tid == 0) {
            float s = 0.0f;
            #pragma unroll
            for (int w = 0; w < 8; ++w) s += swsum[w];
            sv[q] = s;
        }
        __syncthreads();
    }

    if (tid == 0) {
        const float loss1 = sv[0] / (float)N;
        const float denom = fmaxf(sv[2], 1.0f);
        const float loss2 = CE_COEFF * (sv[1] / denom);
        g_batch_loss[b] = loss1 + loss2;
    }
}

__global__ void finalize_kernel(float* __restrict__ out) {
    __shared__ float s[BATCH];
    const int t = threadIdx.x;
    s[t] = g_batch_loss[t];
    __syncthreads();
    #pragma unroll
    for (int off = BATCH / 2; off > 0; off >>= 1) {
        if (t < off) s[t] += s[t + off];
        __syncthreads();
    }
    if (t == 0) out[0] = s[0];
}

extern "C" void kernel_launch(void* const* d_in, const int* in_sizes, int n_in,
                              void* d_out, int out_size) {
    (void)in_sizes; (void)n_in; (void)out_size;
    const float* set1 = (const float*)d_in[0];
    const float* set2 = (const float*)d_in[1];
    float* out = (float*)d_out;

    hungarian_loss_kernel<<<BATCH, N>>>(set1, set2);
    finalize_kernel<<<1, BATCH>>>(out);
}

// round 7
// speedup vs baseline: 5.5822x; 1.1562x over previous
#include <cuda_runtime.h>
#include <math.h>

#define BATCH 128
#define N 256
#define NP1 (N + 1)
#define NUM_CLASSES 8
#define CE_COEFF 10.0f
#define UNCLAIMED 0x7FFFFFFF
#define BIGF 1e30f
#define VMASK 0xFFFFFF00u

__device__ float g_batch_loss[BATCH];

__device__ __forceinline__ float fsqrt_approx(float x) {
    float r;
    asm("sqrt.approx.f32 %0, %1;" : "=f"(r) : "f"(x));
    return r;
}
__device__ __forceinline__ unsigned umin2(unsigned a, unsigned b) { return a < b ? a : b; }

// One CTA per batch, 256 threads, thread tid owns column j = tid+1 (1-based).
// Phase 1  : column reduction (v[j] = min_i cost, greedy row claim).
// Phase 1.5: JV augmenting row reduction (2 passes), packed-REDUX argmin.
// Phase 2  : exact shortest-augmenting-path; BRANCHLESS inner loop (selects
//            only), packed argmin, fused row table, way kept in register.
// Phase 3  : fused loss epilogue.
__global__ __launch_bounds__(N, 1) void hungarian_loss_kernel(
    const float* __restrict__ set1,   // [B, N, 3]
    const float* __restrict__ set2)   // [B, N, 10]
{
    const int b    = blockIdx.x;
    const int tid  = threadIdx.x;
    const int lane = tid & 31;
    const int wid  = tid >> 5;
    const int j    = tid + 1;         // 1-based column id

    __shared__ float s1x[N], s1y[N], s1l[N];
    __shared__ float s2x[N], s2y[N];
    __shared__ float u[NP1];                     // row duals (1-based rows)
    __shared__ __align__(16) float4 rowdat[NP1]; // per column j: {x,y,u,row} of p[j]
    __shared__ int   way[NP1];                   // predecessor column (written post-loop)
    __shared__ int   rowclaim[N];
    __shared__ int   listA[N], listB[N];
    __shared__ unsigned warpmask[8];
    __shared__ int   snfree, snext;
    __shared__ __align__(16) unsigned red1[2][8];
    __shared__ __align__(16) unsigned red2s[2][8];
    __shared__ float swsum[8];

    const float* s1p = set1 + (size_t)b * N * 3;
    const float* s2p = set2 + (size_t)b * N * 10;

    s1x[tid] = s1p[tid * 3 + 0];
    s1y[tid] = s1p[tid * 3 + 1];
    s1l[tid] = s1p[tid * 3 + 2];
    s2x[tid] = s2p[tid * 10 + 0];
    s2y[tid] = s2p[tid * 10 + 1];
    u[tid]   = 0.0f;
    rowdat[tid] = make_float4(0.f, 0.f, 0.f, __int_as_float(0));
    rowclaim[tid] = UNCLAIMED;
    if (tid == 0) { u[N] = 0.0f; rowdat[N] = make_float4(0.f, 0.f, 0.f, __int_as_float(0)); }
    __syncthreads();

    const float c2x = s2x[tid];
    const float c2y = s2y[tid];
    float v;                          // column dual, register-resident

    // ---- Phase 1: column reduction ----
    {
        float bestd2 = BIGF;
        int   besti  = 0;
        #pragma unroll 4
        for (int i = 0; i < N; ++i) {
            const float dx = s1x[i] - c2x;
            const float dy = s1y[i] - c2y;
            const float d2 = fmaf(dx, dx, dy * dy);
            if (d2 < bestd2) { bestd2 = d2; besti = i; }
        }
        v = fsqrt_approx(fmaxf(bestd2, 0.0f));
        atomicMin(&rowclaim[besti], tid);       // deterministic: smallest col wins
        __syncthreads();
        if (rowclaim[besti] == tid)
            rowdat[j] = make_float4(s1x[besti], s1y[besti], 0.0f, __int_as_float(besti + 1));
        const bool isfree = (rowclaim[tid] == UNCLAIMED);   // row = tid
        const unsigned wm = __ballot_sync(0xffffffffu, isfree);
        if (lane == 0) warpmask[wid] = wm;
        __syncthreads();
        int base = 0, tot = 0;
        #pragma unroll
        for (int w = 0; w < 8; ++w) {
            const int c = __popc(warpmask[w]);
            if (w < wid) base += c;
            tot += c;
        }
        if (isfree) listA[base + __popc(wm & ((1u << lane) - 1u))] = tid + 1;
        if (tid == 0) snfree = tot;
        __syncthreads();
    }

    // ---- Phase 1.5: augmenting row reduction (2 passes) ----
    int ncur = snfree;
    {
        int par = 0;
        for (int run = 0; run < 2; ++run) {
            int* cur = (run == 0) ? listA : listB;
            int* nxt = (run == 0) ? listB : listA;
            if (tid == 0) snext = 0;
            __syncthreads();
            for (int t = 0; t < ncur; ++t) {
                const int i = cur[t];
                const float dx = s1x[i - 1] - c2x;
                const float dy = s1y[i - 1] - c2y;
                const float rc = fmaxf(fsqrt_approx(fmaf(dx, dx, dy * dy)) - v, 0.0f);
                const unsigned bits = (__float_as_uint(rc) & VMASK) | (unsigned)tid;
                const unsigned m1w  = __reduce_min_sync(0xffffffffu, bits);
                const unsigned b2   = (bits == m1w) ? 0xFFFFFFFFu : bits;
                const unsigned m2w  = __reduce_min_sync(0xffffffffu, b2);
                if (lane == 0) { red1[par][wid] = m1w; red2s[par][wid] = m2w; }
                __syncthreads();
                unsigned bp = red1[par][0];
                #pragma unroll
                for (int w = 1; w < 8; ++w) bp = umin2(bp, red1[par][w]);
                unsigned sec = 0xFFFFFFFFu;
                #pragma unroll
                for (int w = 0; w < 8; ++w) {
                    const unsigned o = red1[par][w];
                    sec = umin2(sec, (o == bp) ? red2s[par][w] : o);
                }
                const int   jone = (int)(bp & 0xFFu) + 1;
                const float m1   = __uint_as_float(bp & VMASK);
                const float m2   = __uint_as_float(sec & VMASK);
                if (tid == jone - 1) {            // owner handles all updates (no races)
                    const int k = __float_as_int(rowdat[jone].w);
                    if (m1 < m2) {
                        v -= (m2 - m1);
                        rowdat[jone] = make_float4(s1x[i - 1], s1y[i - 1], m2, __int_as_float(i));
                        u[i] = m2;
                        if (k != 0) { nxt[snext] = k; snext = snext + 1; }
                    } else {                      // truncation tie (rare)
                        if (k == 0) {
                            rowdat[jone] = make_float4(s1x[i - 1], s1y[i - 1], m2, __int_as_float(i));
                            u[i] = m2;
                        } else { nxt[snext] = i; snext = snext + 1; }
                    }
                }
                par ^= 1;
            }
            __syncthreads();
            ncur = snext;
            __syncthreads();
        }
    }
    // remaining free rows now in listA[0..ncur)

    // ---- Phase 2: augmenting paths, all 256 threads, branchless inner loop ----
    for (int idx = 0; idx < ncur; ++idx) {
        const int ifree = listA[idx];           // 1-based free row

        unsigned distbits = 0xFFFFFFFFu;        // packed (bits&VMASK)|tid
        int      wayj  = 0;                     // register-resident predecessor
        bool     used  = false;
        float    dmark = 0.0f;
        int      prow  = 0;

        int   jcur = 0;                         // scan-origin column (0 = virtual)
        int   jfin;                             // final free column
        int   i0   = ifree;
        float rx   = s1x[ifree - 1];
        float ry   = s1y[ifree - 1];
        float u0   = u[ifree];
        float D    = 0.0f;
        int   par  = 0;

        while (true) {
            // branchless mark of the newly-used column
            const bool mark = (j == jcur);
            used  = used | mark;
            dmark = mark ? D  : dmark;
            prow  = mark ? i0 : prow;

            // unconditional scan + select-based relax
            const float dx   = rx - c2x;
            const float dy   = ry - c2y;
            const float cost = fsqrt_approx(fmaf(dx, dx, dy * dy));
            const float cand = fmaxf((D - u0) + (cost - v), D);
            const unsigned cb = (__float_as_uint(cand) & VMASK) | (unsigned)tid;
            const bool better = (cb < distbits) & (!used);
            distbits = better ? cb   : distbits;
            wayj     = better ? jcur : wayj;
            const unsigned mybits = used ? 0xFFFFFFFFu : distbits;

            const unsigned m = __reduce_min_sync(0xffffffffu, mybits);
            if (lane == 0) red1[par][wid] = m;
            __syncthreads();

            const uint4* rp = (const uint4*)&red1[par][0];
            const uint4 a = rp[0], c = rp[1];
            const unsigned best = umin2(umin2(umin2(a.x, a.y), umin2(a.z, a.w)),
                                        umin2(umin2(c.x, c.y), umin2(c.z, c.w)));
            D = __uint_as_float(best & VMASK);
            const int jn = (int)(best & 0xFFu) + 1;

            const float4 rd = rowdat[jn];
            const int pj = __float_as_int(rd.w);
            if (pj == 0) { jfin = jn; break; }  // uniform branch
            jcur = jn;
            i0   = pj;
            rx   = rd.x;
            ry   = rd.y;
            u0   = rd.z;
            par ^= 1;
        }

        way[j] = wayj;                          // publish for the chain walk
        // deferred dual updates (owners)
        if (used) {
            const float diff = D - dmark;
            v -= diff;
            u[prow] += diff;
            rowdat[j].z += diff;
        }
        if (tid == 0) u[ifree] += D;
        __syncthreads();
        if (tid == 0) {
            int jj = jfin;
            while (jj != 0) {
                const int jp = way[jj];
                if (jp == 0) {
                    rowdat[jj] = make_float4(s1x[ifree - 1], s1y[ifree - 1],
                                             u[ifree], __int_as_float(ifree));
                } else {
                    rowdat[jj] = rowdat[jp];    // column jj inherits jp's old row (+dual)
                }
                jj = jp;
            }
        }
        __syncthreads();
    }

    // ---- Phase 3: loss epilogue. Thread tid owns column c = tid. ----
    const float4 rdf = rowdat[j];
    const int r = __float_as_int(rdf.w) - 1;

    const float dxm = rdf.x - c2x;
    const float dym = rdf.y - c2y;
    const float md = fsqrt_approx(fmaxf(fmaf(dxm, dxm, dym * dym), 0.0f));

    float lg[NUM_CLASSES];
    float mx = -1e30f;
    #pragma unroll
    for (int k = 0; k < NUM_CLASSES; ++k) {
        lg[k] = s2p[tid * 10 + 2 + k];
        mx = fmaxf(mx, lg[k]);
    }
    float se = 0.0f;
    #pragma unroll
    for (int k = 0; k < NUM_CLASSES; ++k) se += expf(lg[k] - mx);
    const float lse = mx + logf(se);

    const int  t    = (int)s1l[r];
    const bool mask = (t != -1);
    const int  st   = mask ? ((t < 0) ? 0 : (t >= NUM_CLASSES ? NUM_CLASSES - 1 : t)) : 0;
    const float nll = mask ? (lse - lg[st]) : 0.0f;
    const float cnt = mask ? 1.0f : 0.0f;

    float sv[3] = { md, nll, cnt };
    #pragma unroll
    for (int q = 0; q < 3; ++q) {
        float vv = sv[q];
        #pragma unroll
        for (int off = 16; off > 0; off >>= 1)
            vv += __shfl_down_sync(0xffffffffu, vv, off);
        if (lane == 0) swsum[wid] = vv;
        __syncthreads();
        if (tid == 0) {
            float s = 0.0f;
            #pragma unroll
            for (int w = 0; w < 8; ++w) s += swsum[w];
            sv[q] = s;
        }
        __syncthreads();
    }

    if (tid == 0) {
        const float loss1 = sv[0] / (float)N;
        const float denom = fmaxf(sv[2], 1.0f);
        const float loss2 = CE_COEFF * (sv[1] / denom);
        g_batch_loss[b] = loss1 + loss2;
    }
}

__global__ void finalize_kernel(float* __restrict__ out) {
    __shared__ float s[BATCH];
    const int t = threadIdx.x;
    s[t] = g_batch_loss[t];
    __syncthreads();
    #pragma unroll
    for (int off = BATCH / 2; off > 0; off >>= 1) {
        if (t < off) s[t] += s[t + off];
        __syncthreads();
    }
    if (t == 0) out[0] = s[0];
}

extern "C" void kernel_launch(void* const* d_in, const int* in_sizes, int n_in,
                              void* d_out, int out_size) {
    (void)in_sizes; (void)n_in; (void)out_size;
    const float* set1 = (const float*)d_in[0];
    const float* set2 = (const float*)d_in[1];
    float* out = (float*)d_out;

    hungarian_loss_kernel<<<BATCH, N>>>(set1, set2);
    finalize_kernel<<<1, BATCH>>>(out);
}

// round 8
// speedup vs baseline: 6.5891x; 1.1804x over previous
#include <cuda_runtime.h>
#include <math.h>

#define BATCH 128
#define N 256
#define NT 128
#define NP1 (N + 1)
#define NUM_CLASSES 8
#define CE_COEFF 10.0f
#define UNCLAIMED 0x7FFFFFFF
#define BIGF 1e30f
#define VMASK 0xFFFFFF00u

__device__ float g_batch_loss[BATCH];

__device__ __forceinline__ float fsqrt_approx(float x) {
    float r;
    asm("sqrt.approx.f32 %0, %1;" : "=f"(r) : "f"(x));
    return r;
}
__device__ __forceinline__ unsigned umin2(unsigned a, unsigned b) { return a < b ? a : b; }
__device__ __forceinline__ unsigned umax2(unsigned a, unsigned b) { return a > b ? a : b; }

// One CTA per batch, 128 threads, thread tid owns columns tid and tid+128
// (1-based: j0 = tid+1, j1 = tid+129). 4 warps -> cheap barrier + 4-wide combine.
__global__ __launch_bounds__(NT, 1) void hungarian_loss_kernel(
    const float* __restrict__ set1,   // [B, N, 3]
    const float* __restrict__ set2)   // [B, N, 10]
{
    const int b    = blockIdx.x;
    const int tid  = threadIdx.x;
    const int lane = tid & 31;
    const int wid  = tid >> 5;
    const int j0c  = tid + 1;          // 1-based column ids
    const int j1c  = tid + 129;

    __shared__ float s1x[N], s1y[N], s1l[N];
    __shared__ float s2x[N], s2y[N];
    __shared__ float u[NP1];
    __shared__ __align__(16) float4 rowdat[NP1]; // per column j: {x,y,u,row} of p[j]
    __shared__ int   way[NP1];
    __shared__ int   rowclaim[N];
    __shared__ int   listA[N], listB[N];
    __shared__ unsigned warpmask[8];
    __shared__ int   snfree, snext;
    __shared__ __align__(16) unsigned red1[2][4];
    __shared__ __align__(16) unsigned red2s[2][4];
    __shared__ float swsum[4];

    const float* s1p = set1 + (size_t)b * N * 3;
    const float* s2p = set2 + (size_t)b * N * 10;

    #pragma unroll
    for (int q = 0; q < 2; ++q) {
        const int e = tid + q * NT;
        s1x[e] = s1p[e * 3 + 0];
        s1y[e] = s1p[e * 3 + 1];
        s1l[e] = s1p[e * 3 + 2];
        s2x[e] = s2p[e * 10 + 0];
        s2y[e] = s2p[e * 10 + 1];
        u[e]   = 0.0f;
        rowdat[e + 1] = make_float4(0.f, 0.f, 0.f, __int_as_float(0));
        rowclaim[e]   = UNCLAIMED;
    }
    if (tid == 0) { u[N] = 0.0f; rowdat[0] = make_float4(0.f, 0.f, 0.f, __int_as_float(0)); }
    __syncthreads();

    const float cx0 = s2x[tid],       cy0 = s2y[tid];
    const float cx1 = s2x[tid + NT],  cy1 = s2y[tid + NT];
    float v0, v1;                     // column duals, register-resident

    // ---- Phase 1: column reduction ----
    {
        float bd0 = BIGF, bd1 = BIGF;
        int   bi0 = 0,    bi1 = 0;
        #pragma unroll 4
        for (int i = 0; i < N; ++i) {
            const float sx = s1x[i], sy = s1y[i];
            const float dx0 = sx - cx0, dy0 = sy - cy0;
            const float d20 = fmaf(dx0, dx0, dy0 * dy0);
            if (d20 < bd0) { bd0 = d20; bi0 = i; }
            const float dx1 = sx - cx1, dy1 = sy - cy1;
            const float d21 = fmaf(dx1, dx1, dy1 * dy1);
            if (d21 < bd1) { bd1 = d21; bi1 = i; }
        }
        v0 = fsqrt_approx(fmaxf(bd0, 0.0f));
        v1 = fsqrt_approx(fmaxf(bd1, 0.0f));
        atomicMin(&rowclaim[bi0], tid);         // column id tid
        atomicMin(&rowclaim[bi1], tid + NT);    // column id tid+128
        __syncthreads();
        if (rowclaim[bi0] == tid)
            rowdat[j0c] = make_float4(s1x[bi0], s1y[bi0], 0.0f, __int_as_float(bi0 + 1));
        if (rowclaim[bi1] == tid + NT)
            rowdat[j1c] = make_float4(s1x[bi1], s1y[bi1], 0.0f, __int_as_float(bi1 + 1));
        // ordered free-row list; rows tid and tid+128
        const bool f0 = (rowclaim[tid] == UNCLAIMED);
        const bool f1 = (rowclaim[tid + NT] == UNCLAIMED);
        const unsigned wm0 = __ballot_sync(0xffffffffu, f0);
        const unsigned wm1 = __ballot_sync(0xffffffffu, f1);
        if (lane == 0) { warpmask[wid] = wm0; warpmask[wid + 4] = wm1; }
        __syncthreads();
        int base0 = 0, base1 = 0, tot = 0;
        #pragma unroll
        for (int w = 0; w < 8; ++w) {
            const int c = __popc(warpmask[w]);
            if (w < wid)     base0 += c;
            if (w < wid + 4) base1 += c;
            tot += c;
        }
        const unsigned lm = (1u << lane) - 1u;
        if (f0) listA[base0 + __popc(wm0 & lm)] = tid + 1;
        if (f1) listA[base1 + __popc(wm1 & lm)] = tid + NT + 1;
        if (tid == 0) snfree = tot;
        __syncthreads();
    }

    // ---- Phase 1.5: augmenting row reduction (2 passes) ----
    int ncur = snfree;
    {
        int par = 0;
        for (int run = 0; run < 2; ++run) {
            int* cur = (run == 0) ? listA : listB;
            int* nxt = (run == 0) ? listB : listA;
            if (tid == 0) snext = 0;
            __syncthreads();
            for (int t = 0; t < ncur; ++t) {
                const int i = cur[t];
                const float sx = s1x[i - 1], sy = s1y[i - 1];
                const float dx0 = sx - cx0, dy0 = sy - cy0;
                const float rc0 = fmaxf(fsqrt_approx(fmaf(dx0, dx0, dy0 * dy0)) - v0, 0.0f);
                const float dx1 = sx - cx1, dy1 = sy - cy1;
                const float rc1 = fmaxf(fsqrt_approx(fmaf(dx1, dx1, dy1 * dy1)) - v1, 0.0f);
                const unsigned b0 = (__float_as_uint(rc0) & VMASK) | (unsigned)tid;
                const unsigned b1 = (__float_as_uint(rc1) & VMASK) | (unsigned)(tid + NT);
                const unsigned bmin = umin2(b0, b1);
                const unsigned bmax = umax2(b0, b1);
                const unsigned m1w  = __reduce_min_sync(0xffffffffu, bmin);
                const unsigned b2   = (bmin == m1w) ? bmax : bmin;
                const unsigned m2w  = __reduce_min_sync(0xffffffffu, b2);
                if (lane == 0) { red1[par][wid] = m1w; red2s[par][wid] = m2w; }
                __syncthreads();
                const uint4 r1 = *(const uint4*)&red1[par][0];
                const unsigned bp = umin2(umin2(r1.x, r1.y), umin2(r1.z, r1.w));
                const uint4 r2 = *(const uint4*)&red2s[par][0];
                unsigned sec = 0xFFFFFFFFu;
                sec = umin2(sec, (r1.x == bp) ? r2.x : r1.x);
                sec = umin2(sec, (r1.y == bp) ? r2.y : r1.y);
                sec = umin2(sec, (r1.z == bp) ? r2.z : r1.z);
                sec = umin2(sec, (r1.w == bp) ? r2.w : r1.w);
                const int   jone = (int)(bp & 0xFFu) + 1;
                const float m1   = __uint_as_float(bp & VMASK);
                const float m2   = __uint_as_float(sec & VMASK);
                if (tid == ((jone - 1) & (NT - 1))) {   // owner thread
                    const int k = __float_as_int(rowdat[jone].w);
                    if (m1 < m2) {
                        if (jone - 1 < NT) v0 -= (m2 - m1); else v1 -= (m2 - m1);
                        rowdat[jone] = make_float4(sx, sy, m2, __int_as_float(i));
                        u[i] = m2;
                        if (k != 0) { nxt[snext] = k; snext = snext + 1; }
                    } else {
                        if (k == 0) {
                            rowdat[jone] = make_float4(sx, sy, m2, __int_as_float(i));
                            u[i] = m2;
                        } else { nxt[snext] = i; snext = snext + 1; }
                    }
                }
                par ^= 1;
            }
            __syncthreads();
            ncur = snext;
            __syncthreads();
        }
    }
    // remaining free rows now in listA[0..ncur)

    // ---- Phase 2: augmenting paths, branchless inner loop ----
    for (int idx = 0; idx < ncur; ++idx) {
        const int ifree = listA[idx];

        unsigned db0 = 0xFFFFFFFFu, db1 = 0xFFFFFFFFu;
        int   way0 = 0, way1 = 0;
        bool  used0 = false, used1 = false;
        float dm0 = 0.0f, dm1 = 0.0f;
        int   pr0 = 0, pr1 = 0;

        int   jcur = 0;
        int   jfin;
        int   i0   = ifree;
        float rx   = s1x[ifree - 1];
        float ry   = s1y[ifree - 1];
        float u0   = u[ifree];
        float D    = 0.0f;
        int   par  = 0;

        while (true) {
            const bool mk0 = (j0c == jcur);
            used0 |= mk0;  dm0 = mk0 ? D : dm0;  pr0 = mk0 ? i0 : pr0;
            const bool mk1 = (j1c == jcur);
            used1 |= mk1;  dm1 = mk1 ? D : dm1;  pr1 = mk1 ? i0 : pr1;

            const float base = D - u0;
            const float dx0 = rx - cx0, dy0 = ry - cy0;
            const float c0  = fsqrt_approx(fmaf(dx0, dx0, dy0 * dy0));
            const float cand0 = fmaxf(base + (c0 - v0), D);
            const float dx1 = rx - cx1, dy1 = ry - cy1;
            const float c1  = fsqrt_approx(fmaf(dx1, dx1, dy1 * dy1));
            const float cand1 = fmaxf(base + (c1 - v1), D);

            const unsigned cb0 = (__float_as_uint(cand0) & VMASK) | (unsigned)tid;
            const bool be0 = (cb0 < db0) & (!used0);
            db0  = be0 ? cb0  : db0;
            way0 = be0 ? jcur : way0;
            const unsigned cb1 = (__float_as_uint(cand1) & VMASK) | (unsigned)(tid + NT);
            const bool be1 = (cb1 < db1) & (!used1);
            db1  = be1 ? cb1  : db1;
            way1 = be1 ? jcur : way1;

            const unsigned my0 = used0 ? 0xFFFFFFFFu : db0;
            const unsigned my1 = used1 ? 0xFFFFFFFFu : db1;
            const unsigned m = __reduce_min_sync(0xffffffffu, umin2(my0, my1));
            if (lane == 0) red1[par][wid] = m;
            __syncthreads();

            const uint4 r1 = *(const uint4*)&red1[par][0];
            const unsigned best = umin2(umin2(r1.x, r1.y), umin2(r1.z, r1.w));
            D = __uint_as_float(best & VMASK);
            const int jn = (int)(best & 0xFFu) + 1;

            const float4 rd = rowdat[jn];
            const int pj = __float_as_int(rd.w);
            if (pj == 0) { jfin = jn; break; }   // uniform branch
            jcur = jn;
            i0   = pj;
            rx   = rd.x;
            ry   = rd.y;
            u0   = rd.z;
            par ^= 1;
        }

        way[j0c] = way0;
        way[j1c] = way1;
        if (used0) {
            const float diff = D - dm0;
            v0 -= diff;
            u[pr0] += diff;
            rowdat[j0c].z += diff;
        }
        if (used1) {
            const float diff = D - dm1;
            v1 -= diff;
            u[pr1] += diff;
            rowdat[j1c].z += diff;
        }
        if (tid == 0) u[ifree] += D;
        __syncthreads();
        if (tid == 0) {
            int jj = jfin;
            while (jj != 0) {
                const int jp = way[jj];
                if (jp == 0) {
                    rowdat[jj] = make_float4(s1x[ifree - 1], s1y[ifree - 1],
                                             u[ifree], __int_as_float(ifree));
                } else {
                    rowdat[jj] = rowdat[jp];
                }
                jj = jp;
            }
        }
        __syncthreads();
    }

    // ---- Phase 3: loss epilogue, 2 columns per thread ----
    float mds = 0.0f, nlls = 0.0f, cnts = 0.0f;
    #pragma unroll
    for (int q = 0; q < 2; ++q) {
        const int col = tid + q * NT;
        const float4 rdf = rowdat[col + 1];
        const int r = __float_as_int(rdf.w) - 1;

        const float dxm = rdf.x - s2x[col];
        const float dym = rdf.y - s2y[col];
        mds += fsqrt_approx(fmaxf(fmaf(dxm, dxm, dym * dym), 0.0f));

        float lg[NUM_CLASSES];
        float mx = -1e30f;
        #pragma unroll
        for (int k = 0; k < NUM_CLASSES; ++k) {
            lg[k] = s2p[col * 10 + 2 + k];
            mx = fmaxf(mx, lg[k]);
        }
        float se = 0.0f;
        #pragma unroll
        for (int k = 0; k < NUM_CLASSES; ++k) se += expf(lg[k] - mx);
        const float lse = mx + logf(se);

        const int  t    = (int)s1l[r];
        const bool mask = (t != -1);
        const int  st   = mask ? ((t < 0) ? 0 : (t >= NUM_CLASSES ? NUM_CLASSES - 1 : t)) : 0;
        nlls += mask ? (lse - lg[st]) : 0.0f;
        cnts += mask ? 1.0f : 0.0f;
    }

    float sv[3] = { mds, nlls, cnts };
    #pragma unroll
    for (int q = 0; q < 3; ++q) {
        float vv = sv[q];
        #pragma unroll
        for (int off = 16; off > 0; off >>= 1)
            vv += __shfl_down_sync(0xffffffffu, vv, off);
        if (lane == 0) swsum[wid] = vv;
        __syncthreads();
        if (tid == 0) sv[q] = swsum[0] + swsum[1] + swsum[2] + swsum[3];
        __syncthreads();
    }

    if (tid == 0) {
        const float loss1 = sv[0] / (float)N;
        const float denom = fmaxf(sv[2], 1.0f);
        const float loss2 = CE_COEFF * (sv[1] / denom);
        g_batch_loss[b] = loss1 + loss2;
    }
}

__global__ void finalize_kernel(float* __restrict__ out) {
    __shared__ float s[BATCH];
    const int t = threadIdx.x;
    s[t] = g_batch_loss[t];
    __syncthreads();
    #pragma unroll
    for (int off = BATCH / 2; off > 0; off >>= 1) {
        if (t < off) s[t] += s[t + off];
        __syncthreads();
    }
    if (t == 0) out[0] = s[0];
}

extern "C" void kernel_launch(void* const* d_in, const int* in_sizes, int n_in,
                              void* d_out, int out_size) {
    (void)in_sizes; (void)n_in; (void)out_size;
    const float* set1 = (const float*)d_in[0];
    const float* set2 = (const float*)d_in[1];
    float* out = (float*)d_out;

    hungarian_loss_kernel<<<BATCH, NT>>>(set1, set2);
    finalize_kernel<<<1, BATCH>>>(out);
}